// round 15
// baseline (speedup 1.0000x reference)
#include <cuda_runtime.h>
#include <cuda_fp16.h>

#define FCH 32    // node feature channels
#define SCH 16    // edge feature channels
#define SG  17    // s-groups incl. bias slot
#define ZW  (SG*FCH)   // 544
#define N_MAX 50048
#define E_MAX 200704
#define GRP 128        // nodes per block group (fused kernel)
#define TPB 512
#define ZROW 1168      // sZ row stride B (292 words; 292 mod 32 = 4 -> spread banks)

// Scratch (device globals; no allocation allowed)
__device__ float d_h[(size_t)N_MAX * FCH];     // layer-1 output
__device__ float d_agg[(size_t)N_MAX * FCH];   // scatter accumulator
__device__ float d_pooled[FCH];
// edge sort (by src) scratch. d_cnt is zero-initialized at module load and
// re-zeroed inside k_scan after use -> invariant: zero at every k_hist.
__device__ int   d_cnt[N_MAX];
__device__ int   d_off[N_MAX];
__device__ int   d_rowstart[N_MAX + 1];
__device__ int   d_esrc[E_MAX];
__device__ int   d_edst[E_MAX];
__device__ float d_ef2[(size_t)E_MAX * SCH];

// ---------------------------------------------------------------------------
// Edge sort by src: histogram -> 1-block scan (re-zeroes cnt) -> scatter.
// ---------------------------------------------------------------------------
__global__ void k_hist(const int* __restrict__ src, int E)
{
    int e = blockIdx.x * blockDim.x + threadIdx.x;
    if (e < E) atomicAdd(&d_cnt[src[e]], 1);
}

__global__ __launch_bounds__(1024) void k_scan(int N, int E)
{
    __shared__ int sSum[1024];
    int t = threadIdx.x;
    int chunk = (N + 1023) >> 10;
    int lo = t * chunk;
    int hi = lo + chunk < N ? lo + chunk : N;
    int s = 0;
    for (int i = lo; i < hi; i++) s += d_cnt[i];
    sSum[t] = s;
    __syncthreads();
    for (int d = 1; d < 1024; d <<= 1) {
        int v = (t >= d) ? sSum[t - d] : 0;
        __syncthreads();
        if (t >= d) sSum[t] += v;
        __syncthreads();
    }
    int base = (t == 0) ? 0 : sSum[t - 1];   // exclusive prefix of chunk
    for (int i = lo; i < hi; i++) {
        int c = d_cnt[i];
        d_off[i] = base;
        d_rowstart[i] = base;
        base += c;
        d_cnt[i] = 0;                        // restore invariant for next call
    }
    if (t == 0) d_rowstart[N] = E;
}

// scatter + zero d_agg + zero d_pooled
__global__ __launch_bounds__(256) void k_scatter(
    const float* __restrict__ ef, const int* __restrict__ src,
    const int* __restrict__ dst, int E, int N)
{
    int tid  = blockIdx.x * blockDim.x + threadIdx.x;
    int za = tid * 2;
    if (za < N * FCH) {
        d_agg[za] = 0.f;
        if (za + 1 < N * FCH) d_agg[za + 1] = 0.f;
    }
    if (tid < FCH) d_pooled[tid] = 0.f;

    int edge = tid >> 2;
    int lane = threadIdx.x & 31;
    int sub  = lane & 3;
    bool valid = edge < E;
    int p = 0;
    int sn = 0;
    if (valid) {
        sn = src[edge];
        if (sub == 0) p = atomicAdd(&d_off[sn], 1);
    }
    p = __shfl_sync(0xffffffffu, p, lane & 28);
    if (!valid) return;
    if (sub == 0) { d_esrc[p] = sn; d_edst[p] = dst[edge]; }
    float4 v = ((const float4*)(ef + (size_t)edge * SCH))[sub];
    ((float4*)(d_ef2 + (size_t)p * SCH))[sub] = v;
}

// ---------------------------------------------------------------------------
// FUSED layer kernel: per block group of GRP=128 nodes:
//   Phase A: Z tile (17 s-groups x 32 ch, fp16) into SMEM via HFMA2.
//            2 nodes per thread; x packed as channel-pair half2.
//   Phase B: group's contiguous (src-sorted) edge range, Z from SMEM,
//            software-pipelined (next iter's LDGs prefetched), scatter via
//            red.global.add.v4.
// ---------------------------------------------------------------------------
__global__ __launch_bounds__(TPB, 1) void k_layer(
    const float* __restrict__ h_ext, const float* __restrict__ fgn_w,
    const float* __restrict__ fgn_b, int N, int use_dh)
{
    extern __shared__ char smem[];
    __half* sWh = (__half*)smem;                    // [FCH][ZW] halves = 34816 B
    char*   sZ  = smem + (size_t)FCH * ZW * 2;      // GRP rows * ZROW B

    for (int i = threadIdx.x; i < FCH * ZW; i += TPB) {
        int k = i / ZW;
        int j = i - k * ZW;
        int s = j >> 5, o = j & 31;
        float v = (s < SCH) ? fgn_w[s * (FCH * FCH) + k * FCH + o]
                            : fgn_b[k * FCH + o];
        sWh[i] = __float2half(v);
    }
    __syncthreads();

    const float* h = use_dh ? d_h : h_ext;

    int i_node = threadIdx.x >> 3;   // 0..63
    int sub    = threadIdx.x & 7;    // o-chunk of 4 ch
    int lane   = threadIdx.x & 31;
    int warpInBlk = threadIdx.x >> 5;   // 0..15
    int g    = lane >> 2;            // edge slot in warp (0..7)
    int esub = lane & 3;             // 8-ch chunk for edges
    const int estep = (TPB / 32) * 8;

    for (int g0 = blockIdx.x * GRP; g0 < N; g0 += gridDim.x * GRP) {
        // ----- Phase A: Z tile into SMEM (2 nodes per thread) ---------------
        int nA = g0 + i_node;
        int nB = g0 + i_node + 64;
        {
            int rA = nA < N ? nA : N - 1;
            int rB = nB < N ? nB : N - 1;
            __half2 xpA[FCH / 2], xpB[FCH / 2];   // channel pairs (x2i, x2i+1)
            const float4* pa = (const float4*)(h + (size_t)rA * FCH);
            const float4* pb = (const float4*)(h + (size_t)rB * FCH);
            #pragma unroll
            for (int i = 0; i < FCH / 4; i++) {
                float4 v = pa[i];
                xpA[2*i]   = __floats2half2_rn(v.x, v.y);
                xpA[2*i+1] = __floats2half2_rn(v.z, v.w);
            }
            #pragma unroll
            for (int i = 0; i < FCH / 4; i++) {
                float4 v = pb[i];
                xpB[2*i]   = __floats2half2_rn(v.x, v.y);
                xpB[2*i+1] = __floats2half2_rn(v.z, v.w);
            }
            char* zA = sZ + (size_t)i_node * ZROW;
            char* zB = sZ + (size_t)(i_node + 64) * ZROW;
            #pragma unroll 1
            for (int s = 0; s < SG; s++) {
                const uint2* wp = (const uint2*)sWh + s * 8 + sub;  // 4 halves
                __half2 a0 = __float2half2_rn(0.f);
                __half2 a1 = __float2half2_rn(0.f);
                __half2 b0 = __float2half2_rn(0.f);
                __half2 b1 = __float2half2_rn(0.f);
                #pragma unroll
                for (int i = 0; i < FCH / 2; i++) {
                    uint2 w0 = wp[(2*i)     * (ZW / 4)];   // k = 2i
                    uint2 w1 = wp[(2*i + 1) * (ZW / 4)];   // k = 2i+1
                    __half2 w00 = *(const __half2*)&w0.x;
                    __half2 w01 = *(const __half2*)&w0.y;
                    __half2 w10 = *(const __half2*)&w1.x;
                    __half2 w11 = *(const __half2*)&w1.y;
                    __half2 xaL = __low2half2(xpA[i]);
                    __half2 xaH = __high2half2(xpA[i]);
                    __half2 xbL = __low2half2(xpB[i]);
                    __half2 xbH = __high2half2(xpB[i]);
                    a0 = __hfma2(xaL, w00, a0);
                    a1 = __hfma2(xaL, w01, a1);
                    b0 = __hfma2(xbL, w00, b0);
                    b1 = __hfma2(xbL, w01, b1);
                    a0 = __hfma2(xaH, w10, a0);
                    a1 = __hfma2(xaH, w11, a1);
                    b0 = __hfma2(xbH, w10, b0);
                    b1 = __hfma2(xbH, w11, b1);
                }
                uint2 ra, rb;
                ra.x = *(const unsigned int*)&a0;
                ra.y = *(const unsigned int*)&a1;
                rb.x = *(const unsigned int*)&b0;
                rb.y = *(const unsigned int*)&b1;
                if (nA < N) *(uint2*)(zA + s * 64 + sub * 8) = ra;
                if (nB < N) *(uint2*)(zB + s * 64 + sub * 8) = rb;
            }
        }
        __syncthreads();

        // ----- Phase B: edges, software-pipelined ---------------------------
        int gHi = g0 + GRP < N ? g0 + GRP : N;
        int eLo = d_rowstart[g0];
        int eHi = d_rowstart[gHi];
        int base = eLo + warpInBlk * 8;
        if (base < eHi) {
            // prime iteration 0
            int edge = base + g;
            bool valid = edge < eHi;
            int ce = valid ? edge : eHi - 1;
            float4 es = ((const float4*)(d_ef2 + (size_t)ce * SCH))[esub];
            int ln = d_esrc[ce] - g0;
            int dn = d_edst[ce];

            while (base < eHi) {
                int nbase = base + estep;
                // prefetch next iteration's global data
                float4 es_n = es;
                int ln_n = 0, dn_n = 0;
                bool valid_n = false;
                if (nbase < eHi) {
                    int edge_n = nbase + g;
                    valid_n = edge_n < eHi;
                    int ce_n = valid_n ? edge_n : eHi - 1;
                    es_n = ((const float4*)(d_ef2 + (size_t)ce_n * SCH))[esub];
                    ln_n = d_esrc[ce_n] - g0;
                    dn_n = d_edst[ce_n];
                }

                // compute current
                const char* zb = sZ + (size_t)ln * ZROW + esub * 16;
                uint4 z16 = *(const uint4*)(zb + 16 * 64);   // bias slot init
                __half2 acc0 = *(const __half2*)&z16.x;
                __half2 acc1 = *(const __half2*)&z16.y;
                __half2 acc2 = *(const __half2*)&z16.z;
                __half2 acc3 = *(const __half2*)&z16.w;

                #pragma unroll
                for (int s = 0; s < SCH; s++) {
                    float comp = ((s & 3) == 0) ? es.x : ((s & 3) == 1) ? es.y
                               : ((s & 3) == 2) ? es.z : es.w;
                    float c = __shfl_sync(0xffffffffu, comp, (lane & 28) | (s >> 2));
                    __half2 c2 = __float2half2_rn(c);
                    uint4 zv = *(const uint4*)(zb + s * 64);
                    acc0 = __hfma2(c2, *(const __half2*)&zv.x, acc0);
                    acc1 = __hfma2(c2, *(const __half2*)&zv.y, acc1);
                    acc2 = __hfma2(c2, *(const __half2*)&zv.z, acc2);
                    acc3 = __hfma2(c2, *(const __half2*)&zv.w, acc3);
                }

                if (valid) {
                    float2 f0 = __half22float2(acc0);
                    float2 f1 = __half22float2(acc1);
                    float2 f2 = __half22float2(acc2);
                    float2 f3 = __half22float2(acc3);
                    float* a = d_agg + (size_t)dn * FCH + esub * 8;
                    asm volatile("red.global.add.v4.f32 [%0], {%1, %2, %3, %4};"
                                 :: "l"(a), "f"(f0.x), "f"(f0.y), "f"(f1.x), "f"(f1.y)
                                 : "memory");
                    asm volatile("red.global.add.v4.f32 [%0], {%1, %2, %3, %4};"
                                 :: "l"(a + 4), "f"(f2.x), "f"(f2.y), "f"(f3.x), "f"(f3.y)
                                 : "memory");
                }

                base = nbase;
                es = es_n; ln = ln_n; dn = dn_n; valid = valid_n;
            }
        }
        __syncthreads();
    }
}

// ---------------------------------------------------------------------------
// K3: hout[n] = relu(agg[n] + h[n] @ root + bias). do_pool: accumulate into
//     d_pooled instead of storing. zero_agg: re-zero agg rows for next layer.
// ---------------------------------------------------------------------------
__global__ __launch_bounds__(256) void k_node(
    const float* __restrict__ hin_ext, const float* __restrict__ root,
    const float* __restrict__ bias, int N, int use_dh, int do_pool, int zero_agg)
{
    __shared__ float sR[FCH * FCH];
    __shared__ float sB[FCH];
    __shared__ float sPool[FCH];
    for (int i = threadIdx.x; i < FCH * FCH; i += blockDim.x) sR[i] = root[i];
    if (threadIdx.x < FCH) { sB[threadIdx.x] = bias[threadIdx.x]; sPool[threadIdx.x] = 0.f; }
    __syncthreads();

    const float* hin = use_dh ? d_h : hin_ext;
    const float4* sR4 = (const float4*)sR;
    const float4* sB4 = (const float4*)sB;
    int lane = threadIdx.x & 31;

    float pacc[FCH];
    #pragma unroll
    for (int i = 0; i < FCH; i++) pacc[i] = 0.f;

    for (int n = blockIdx.x * blockDim.x + threadIdx.x; n < N;
         n += gridDim.x * blockDim.x) {
        float xr[FCH];
        const float4* hp = (const float4*)(hin + (size_t)n * FCH);
        #pragma unroll
        for (int i = 0; i < FCH / 4; i++) {
            float4 v = hp[i];
            xr[4*i+0] = v.x; xr[4*i+1] = v.y; xr[4*i+2] = v.z; xr[4*i+3] = v.w;
        }
        float4* ag = (float4*)(d_agg + (size_t)n * FCH);
        float4* op = (float4*)(d_h + (size_t)n * FCH);
        #pragma unroll
        for (int o4 = 0; o4 < FCH / 4; o4++) {
            float4 a = ag[o4];
            float4 b = sB4[o4];
            float4 acc = make_float4(a.x + b.x, a.y + b.y, a.z + b.z, a.w + b.w);
            #pragma unroll
            for (int k = 0; k < FCH; k++) {
                float4 w = sR4[k * (FCH / 4) + o4];
                acc.x = fmaf(xr[k], w.x, acc.x);
                acc.y = fmaf(xr[k], w.y, acc.y);
                acc.z = fmaf(xr[k], w.z, acc.z);
                acc.w = fmaf(xr[k], w.w, acc.w);
            }
            acc.x = fmaxf(acc.x, 0.f);
            acc.y = fmaxf(acc.y, 0.f);
            acc.z = fmaxf(acc.z, 0.f);
            acc.w = fmaxf(acc.w, 0.f);
            if (zero_agg) ag[o4] = make_float4(0.f, 0.f, 0.f, 0.f);
            if (do_pool) {
                pacc[4*o4+0] += acc.x; pacc[4*o4+1] += acc.y;
                pacc[4*o4+2] += acc.z; pacc[4*o4+3] += acc.w;
            } else {
                op[o4] = acc;
            }
        }
    }

    if (do_pool) {
        #pragma unroll
        for (int j = 0; j < FCH; j++) {
            int o = (lane + j) & 31;
            atomicAdd(&sPool[o], pacc[o]);
        }
        __syncthreads();
        if (threadIdx.x < FCH)
            atomicAdd(&d_pooled[threadIdx.x], sPool[threadIdx.x]);
    }
}

// ---------------------------------------------------------------------------
// Final: out[0] = pooled . dense_w + dense_b
// ---------------------------------------------------------------------------
__global__ void k_final(const float* __restrict__ dw, const float* __restrict__ db,
                        float* __restrict__ out)
{
    int l = threadIdx.x;
    float v = (l < FCH) ? d_pooled[l] * dw[l] : 0.f;
    #pragma unroll
    for (int off = 16; off > 0; off >>= 1)
        v += __shfl_down_sync(0xffffffffu, v, off);
    if (l == 0) out[0] = v + db[0];
}

extern "C" void kernel_launch(void* const* d_in, const int* in_sizes, int n_in,
                              void* d_out, int out_size)
{
    const float* x      = (const float*)d_in[0];
    const float* e      = (const float*)d_in[1];
    const int*   src    = (const int*)d_in[2];
    const int*   dst    = (const int*)d_in[3];
    const float* fgn_w1 = (const float*)d_in[4];
    const float* fgn_b1 = (const float*)d_in[5];
    const float* root1  = (const float*)d_in[6];
    const float* bias1  = (const float*)d_in[7];
    const float* fgn_w2 = (const float*)d_in[8];
    const float* fgn_b2 = (const float*)d_in[9];
    const float* root2  = (const float*)d_in[10];
    const float* bias2  = (const float*)d_in[11];
    const float* dw     = (const float*)d_in[12];
    const float* db     = (const float*)d_in[13];

    int N = in_sizes[0] / FCH;
    int E = in_sizes[2];
    if (N > N_MAX) N = N_MAX;
    if (E > E_MAX) E = E_MAX;

    size_t smemL = (size_t)FCH * ZW * 2 + (size_t)GRP * ZROW;  // 34816+149504=184320
    cudaFuncSetAttribute(k_layer, cudaFuncAttributeMaxDynamicSharedMemorySize,
                         (int)smemL);

    const int LB = 148;                     // persistent: 1 block/SM
    const int NB = 444;                     // node-kernel blocks (grid-stride)
    const int EB = (E * 4 + 255) / 256;     // scatter: 4 threads per edge

    // Build src-sorted CSR. d_cnt arrives zeroed (module init / k_scan);
    // launch order puts k_layer at capture index 3 for ncu.
    k_hist<<<(E + 255) / 256, 256>>>(src, E);
    k_scan<<<1, 1024>>>(N, E);
    k_scatter<<<EB, 256>>>(e, src, dst, E, N);

    // Layer 1 (fused expand+edge)  <- ncu capture lands here (launch idx 3)
    k_layer<<<LB, TPB, smemL>>>(x, fgn_w1, fgn_b1, N, 0);
    k_node<<<NB, 256>>>(x, root1, bias1, N, 0, 0, 1);   // -> d_h, agg=0

    // Layer 2
    k_layer<<<LB, TPB, smemL>>>(x, fgn_w2, fgn_b2, N, 1);
    k_node<<<NB, 256>>>(x, root2, bias2, N, 1, 1, 0);   // -> d_pooled

    k_final<<<1, 32>>>(dw, db, (float*)d_out);
}

// round 17
// speedup vs baseline: 1.1836x; 1.1836x over previous
#include <cuda_runtime.h>
#include <cuda_fp16.h>

#define FCH 32    // node feature channels
#define SCH 16    // edge feature channels
#define SG  17    // s-groups incl. bias slot
#define ZW  (SG*FCH)   // 544
#define N_MAX 50048
#define E_MAX 200704
#define GRP 128        // nodes per block group (fused kernel)
#define TPB 512
#define ZROW 1168      // sZ row stride B (292 words; 292 mod 32 = 4 -> spread banks)

// Scratch (device globals; no allocation allowed)
__device__ float d_h[(size_t)N_MAX * FCH];     // layer-1 output
__device__ float d_agg[(size_t)N_MAX * FCH];   // scatter accumulator
__device__ float d_pooled[FCH];
// edge sort (by src) scratch. d_cnt is zero-initialized at module load and
// re-zeroed inside k_scan after use -> invariant: zero at every k_hist.
__device__ int   d_cnt[N_MAX];
__device__ int   d_off[N_MAX];
__device__ int   d_rowstart[N_MAX + 1];
__device__ int   d_esrc[E_MAX];
__device__ int   d_edst[E_MAX];
__device__ float d_ef2[(size_t)E_MAX * SCH];

// ---------------------------------------------------------------------------
// Edge sort by src: histogram -> 1-block coalesced scan -> scatter.
// ---------------------------------------------------------------------------
__global__ void k_hist(const int* __restrict__ src, int E)
{
    int e = blockIdx.x * blockDim.x + threadIdx.x;
    if (e < E) atomicAdd(&d_cnt[src[e]], 1);
}

// Coalesced tile-based exclusive scan (1 block, 1024 threads).
// Re-zeroes d_cnt as it goes (invariant for next graph replay).
__global__ __launch_bounds__(1024) void k_scan(int N, int E)
{
    __shared__ int sWarp[32];
    __shared__ int sCarry;
    int t = threadIdx.x, lane = t & 31, wid = t >> 5;
    if (t == 0) sCarry = 0;
    __syncthreads();

    int ntiles = (N + 1023) >> 10;
    for (int tile = 0; tile < ntiles; tile++) {
        int i = tile * 1024 + t;
        int c = (i < N) ? d_cnt[i] : 0;
        // inclusive warp scan
        int x = c;
        #pragma unroll
        for (int d = 1; d < 32; d <<= 1) {
            int v = __shfl_up_sync(0xffffffffu, x, d);
            if (lane >= d) x += v;
        }
        if (lane == 31) sWarp[wid] = x;
        __syncthreads();
        if (wid == 0) {
            int y = sWarp[lane];
            #pragma unroll
            for (int d = 1; d < 32; d <<= 1) {
                int v = __shfl_up_sync(0xffffffffu, y, d);
                if (lane >= d) y += v;
            }
            sWarp[lane] = y;   // inclusive cross-warp
        }
        __syncthreads();
        int base = sCarry + (wid ? sWarp[wid - 1] : 0);
        int excl = base + x - c;
        if (i < N) {
            d_off[i] = excl;
            d_rowstart[i] = excl;
            d_cnt[i] = 0;                  // restore invariant
        }
        __syncthreads();                   // all reads of sCarry/sWarp done
        if (t == 0) sCarry += sWarp[31];
        __syncthreads();                   // carry update ordered before next
                                           // tile's sWarp writes (race fix)
    }
    if (t == 0) d_rowstart[N] = E;
}

// scatter + zero d_agg + zero d_pooled
__global__ __launch_bounds__(256) void k_scatter(
    const float* __restrict__ ef, const int* __restrict__ src,
    const int* __restrict__ dst, int E, int N)
{
    int tid  = blockIdx.x * blockDim.x + threadIdx.x;
    int za = tid * 2;
    if (za < N * FCH) {
        d_agg[za] = 0.f;
        if (za + 1 < N * FCH) d_agg[za + 1] = 0.f;
    }
    if (tid < FCH) d_pooled[tid] = 0.f;

    int edge = tid >> 2;
    int lane = threadIdx.x & 31;
    int sub  = lane & 3;
    bool valid = edge < E;
    int p = 0;
    int sn = 0;
    if (valid) {
        sn = src[edge];
        if (sub == 0) p = atomicAdd(&d_off[sn], 1);
    }
    p = __shfl_sync(0xffffffffu, p, lane & 28);
    if (!valid) return;
    if (sub == 0) { d_esrc[p] = sn; d_edst[p] = dst[edge]; }
    float4 v = ((const float4*)(ef + (size_t)edge * SCH))[sub];
    ((float4*)(d_ef2 + (size_t)p * SCH))[sub] = v;
}

// ---------------------------------------------------------------------------
// FUSED layer kernel: per block group of GRP=128 nodes:
//   Phase A: Z tile (fp16) into SMEM via HFMA2, 2 nodes/thread.
//   Phase B: group's contiguous (src-sorted) edge range, Z from SMEM,
//            scatter messages with red.global.add.v4.
// ---------------------------------------------------------------------------
__global__ __launch_bounds__(TPB, 1) void k_layer(
    const float* __restrict__ h_ext, const float* __restrict__ fgn_w,
    const float* __restrict__ fgn_b, int N, int use_dh)
{
    extern __shared__ char smem[];
    __half* sWh = (__half*)smem;                    // [FCH][ZW] halves = 34816 B
    char*   sZ  = smem + (size_t)FCH * ZW * 2;      // GRP rows * ZROW B

    for (int i = threadIdx.x; i < FCH * ZW; i += TPB) {
        int k = i / ZW;
        int j = i - k * ZW;
        int s = j >> 5, o = j & 31;
        float v = (s < SCH) ? fgn_w[s * (FCH * FCH) + k * FCH + o]
                            : fgn_b[k * FCH + o];
        sWh[i] = __float2half(v);
    }
    __syncthreads();

    const float* h = use_dh ? d_h : h_ext;

    int i_node = threadIdx.x >> 3;   // 0..63
    int sub    = threadIdx.x & 7;    // o-chunk of 4 ch
    int lane   = threadIdx.x & 31;
    int warpInBlk = threadIdx.x >> 5;   // 0..15
    int g    = lane >> 2;            // edge slot in warp (0..7)
    int esub = lane & 3;             // 8-ch chunk for edges

    for (int g0 = blockIdx.x * GRP; g0 < N; g0 += gridDim.x * GRP) {
        // ----- Phase A: Z tile into SMEM (2 nodes per thread) ---------------
        int nA = g0 + i_node;
        int nB = g0 + i_node + 64;
        {
            int rA = nA < N ? nA : N - 1;
            int rB = nB < N ? nB : N - 1;
            __half2 xpA[FCH / 2], xpB[FCH / 2];   // channel pairs (x2i, x2i+1)
            const float4* pa = (const float4*)(h + (size_t)rA * FCH);
            const float4* pb = (const float4*)(h + (size_t)rB * FCH);
            #pragma unroll
            for (int i = 0; i < FCH / 4; i++) {
                float4 v = pa[i];
                xpA[2*i]   = __floats2half2_rn(v.x, v.y);
                xpA[2*i+1] = __floats2half2_rn(v.z, v.w);
            }
            #pragma unroll
            for (int i = 0; i < FCH / 4; i++) {
                float4 v = pb[i];
                xpB[2*i]   = __floats2half2_rn(v.x, v.y);
                xpB[2*i+1] = __floats2half2_rn(v.z, v.w);
            }
            char* zA = sZ + (size_t)i_node * ZROW;
            char* zB = sZ + (size_t)(i_node + 64) * ZROW;
            #pragma unroll 1
            for (int s = 0; s < SG; s++) {
                const uint2* wp = (const uint2*)sWh + s * 8 + sub;  // 4 halves
                __half2 a0 = __float2half2_rn(0.f);
                __half2 a1 = __float2half2_rn(0.f);
                __half2 b0 = __float2half2_rn(0.f);
                __half2 b1 = __float2half2_rn(0.f);
                #pragma unroll
                for (int i = 0; i < FCH / 2; i++) {
                    uint2 w0 = wp[(2*i)     * (ZW / 4)];
                    uint2 w1 = wp[(2*i + 1) * (ZW / 4)];
                    __half2 w00 = *(const __half2*)&w0.x;
                    __half2 w01 = *(const __half2*)&w0.y;
                    __half2 w10 = *(const __half2*)&w1.x;
                    __half2 w11 = *(const __half2*)&w1.y;
                    __half2 xaL = __low2half2(xpA[i]);
                    __half2 xaH = __high2half2(xpA[i]);
                    __half2 xbL = __low2half2(xpB[i]);
                    __half2 xbH = __high2half2(xpB[i]);
                    a0 = __hfma2(xaL, w00, a0);
                    a1 = __hfma2(xaL, w01, a1);
                    b0 = __hfma2(xbL, w00, b0);
                    b1 = __hfma2(xbL, w01, b1);
                    a0 = __hfma2(xaH, w10, a0);
                    a1 = __hfma2(xaH, w11, a1);
                    b0 = __hfma2(xbH, w10, b0);
                    b1 = __hfma2(xbH, w11, b1);
                }
                uint2 ra, rb;
                ra.x = *(const unsigned int*)&a0;
                ra.y = *(const unsigned int*)&a1;
                rb.x = *(const unsigned int*)&b0;
                rb.y = *(const unsigned int*)&b1;
                if (nA < N) *(uint2*)(zA + s * 64 + sub * 8) = ra;
                if (nB < N) *(uint2*)(zB + s * 64 + sub * 8) = rb;
            }
        }
        __syncthreads();

        // ----- Phase B: this group's edges (contiguous, src-sorted) ---------
        int gHi = g0 + GRP < N ? g0 + GRP : N;
        int eLo = d_rowstart[g0];
        int eHi = d_rowstart[gHi];
        for (int base = eLo + warpInBlk * 8; base < eHi; base += (TPB / 32) * 8) {
            int edge = base + g;
            bool valid = edge < eHi;
            int ce = valid ? edge : eHi - 1;        // loop ran => eHi > eLo
            float4 es = ((const float4*)(d_ef2 + (size_t)ce * SCH))[esub];
            int ln = d_esrc[ce] - g0;               // 0..GRP-1
            int dn = d_edst[ce];
            const char* zb = sZ + (size_t)ln * ZROW + esub * 16;

            uint4 z16 = *(const uint4*)(zb + 16 * 64);   // bias slot init
            __half2 acc0 = *(const __half2*)&z16.x;
            __half2 acc1 = *(const __half2*)&z16.y;
            __half2 acc2 = *(const __half2*)&z16.z;
            __half2 acc3 = *(const __half2*)&z16.w;

            #pragma unroll
            for (int s = 0; s < SCH; s++) {
                float comp = ((s & 3) == 0) ? es.x : ((s & 3) == 1) ? es.y
                           : ((s & 3) == 2) ? es.z : es.w;
                float c = __shfl_sync(0xffffffffu, comp, (lane & 28) | (s >> 2));
                __half2 c2 = __float2half2_rn(c);
                uint4 zv = *(const uint4*)(zb + s * 64);
                acc0 = __hfma2(c2, *(const __half2*)&zv.x, acc0);
                acc1 = __hfma2(c2, *(const __half2*)&zv.y, acc1);
                acc2 = __hfma2(c2, *(const __half2*)&zv.z, acc2);
                acc3 = __hfma2(c2, *(const __half2*)&zv.w, acc3);
            }

            if (valid) {
                float2 f0 = __half22float2(acc0);
                float2 f1 = __half22float2(acc1);
                float2 f2 = __half22float2(acc2);
                float2 f3 = __half22float2(acc3);
                float* a = d_agg + (size_t)dn * FCH + esub * 8;
                asm volatile("red.global.add.v4.f32 [%0], {%1, %2, %3, %4};"
                             :: "l"(a), "f"(f0.x), "f"(f0.y), "f"(f1.x), "f"(f1.y)
                             : "memory");
                asm volatile("red.global.add.v4.f32 [%0], {%1, %2, %3, %4};"
                             :: "l"(a + 4), "f"(f2.x), "f"(f2.y), "f"(f3.x), "f"(f3.y)
                             : "memory");
            }
        }
        __syncthreads();
    }
}

// ---------------------------------------------------------------------------
// K3 v2: 8 threads per node, each owns 4 channels. DO_POOL is a template
// param so the non-pool instantiation carries no pool registers.
//   hout[n] = relu(agg[n] + h[n] @ root + bias)
// ---------------------------------------------------------------------------
template <int DO_POOL>
__global__ __launch_bounds__(256) void k_node(
    const float* __restrict__ hin_ext, const float* __restrict__ root,
    const float* __restrict__ bias, int N, int use_dh, int zero_agg)
{
    __shared__ float sR[FCH * FCH];
    __shared__ float sB[FCH];
    __shared__ float sPool[FCH];
    for (int i = threadIdx.x; i < FCH * FCH; i += blockDim.x) sR[i] = root[i];
    if (threadIdx.x < FCH) { sB[threadIdx.x] = bias[threadIdx.x]; sPool[threadIdx.x] = 0.f; }
    __syncthreads();

    const float* hin = use_dh ? d_h : hin_ext;
    const float4* sR4 = (const float4*)sR;   // [k][8 float4 chunks]
    int sub = threadIdx.x & 7;               // channel chunk (4 ch)
    float4 bch = ((const float4*)sB)[sub];

    float4 pacc = make_float4(0.f, 0.f, 0.f, 0.f);

    int tid = blockIdx.x * blockDim.x + threadIdx.x;
    int stride = gridDim.x * blockDim.x;     // multiple of 8
    for (int idx = tid; idx < N * 8; idx += stride) {
        int n = idx >> 3;
        float xr[FCH];
        const float4* hp = (const float4*)(hin + (size_t)n * FCH);
        #pragma unroll
        for (int i = 0; i < FCH / 4; i++) {
            float4 v = hp[i];
            xr[4*i+0] = v.x; xr[4*i+1] = v.y; xr[4*i+2] = v.z; xr[4*i+3] = v.w;
        }
        float4* ag = (float4*)(d_agg + (size_t)n * FCH) + sub;
        float4 a = *ag;
        float4 acc = make_float4(a.x + bch.x, a.y + bch.y, a.z + bch.z, a.w + bch.w);
        #pragma unroll
        for (int k = 0; k < FCH; k++) {
            float4 w = sR4[k * (FCH / 4) + sub];
            acc.x = fmaf(xr[k], w.x, acc.x);
            acc.y = fmaf(xr[k], w.y, acc.y);
            acc.z = fmaf(xr[k], w.z, acc.z);
            acc.w = fmaf(xr[k], w.w, acc.w);
        }
        acc.x = fmaxf(acc.x, 0.f);
        acc.y = fmaxf(acc.y, 0.f);
        acc.z = fmaxf(acc.z, 0.f);
        acc.w = fmaxf(acc.w, 0.f);
        if (zero_agg) *ag = make_float4(0.f, 0.f, 0.f, 0.f);
        if (DO_POOL) {
            pacc.x += acc.x; pacc.y += acc.y; pacc.z += acc.z; pacc.w += acc.w;
        } else {
            ((float4*)(d_h + (size_t)n * FCH))[sub] = acc;
        }
    }

    if (DO_POOL) {
        // block reduce: channels sub*4..sub*4+3; rotate start to spread banks
        int r = (threadIdx.x >> 3) & 3;
        #pragma unroll
        for (int j = 0; j < 4; j++) {
            int jj = (j + r) & 3;
            float v = (jj == 0) ? pacc.x : (jj == 1) ? pacc.y
                    : (jj == 2) ? pacc.z : pacc.w;
            atomicAdd(&sPool[sub * 4 + jj], v);
        }
        __syncthreads();
        if (threadIdx.x < FCH)
            atomicAdd(&d_pooled[threadIdx.x], sPool[threadIdx.x]);
    }
}

// ---------------------------------------------------------------------------
// Final: out[0] = pooled . dense_w + dense_b
// ---------------------------------------------------------------------------
__global__ void k_final(const float* __restrict__ dw, const float* __restrict__ db,
                        float* __restrict__ out)
{
    int l = threadIdx.x;
    float v = (l < FCH) ? d_pooled[l] * dw[l] : 0.f;
    #pragma unroll
    for (int off = 16; off > 0; off >>= 1)
        v += __shfl_down_sync(0xffffffffu, v, off);
    if (l == 0) out[0] = v + db[0];
}

extern "C" void kernel_launch(void* const* d_in, const int* in_sizes, int n_in,
                              void* d_out, int out_size)
{
    const float* x      = (const float*)d_in[0];
    const float* e      = (const float*)d_in[1];
    const int*   src    = (const int*)d_in[2];
    const int*   dst    = (const int*)d_in[3];
    const float* fgn_w1 = (const float*)d_in[4];
    const float* fgn_b1 = (const float*)d_in[5];
    const float* root1  = (const float*)d_in[6];
    const float* bias1  = (const float*)d_in[7];
    const float* fgn_w2 = (const float*)d_in[8];
    const float* fgn_b2 = (const float*)d_in[9];
    const float* root2  = (const float*)d_in[10];
    const float* bias2  = (const float*)d_in[11];
    const float* dw     = (const float*)d_in[12];
    const float* db     = (const float*)d_in[13];

    int N = in_sizes[0] / FCH;
    int E = in_sizes[2];
    if (N > N_MAX) N = N_MAX;
    if (E > E_MAX) E = E_MAX;

    size_t smemL = (size_t)FCH * ZW * 2 + (size_t)GRP * ZROW;  // 184320 B
    cudaFuncSetAttribute(k_layer, cudaFuncAttributeMaxDynamicSharedMemorySize,
                         (int)smemL);

    const int LB = 148;                     // persistent: 1 block/SM
    const int NB = 444;                     // node-kernel blocks (grid-stride)
    const int EB = (E * 4 + 255) / 256;     // scatter: 4 threads per edge

    // Build src-sorted CSR; k_layer stays at capture index 3 for ncu.
    k_hist<<<(E + 255) / 256, 256>>>(src, E);
    k_scan<<<1, 1024>>>(N, E);
    k_scatter<<<EB, 256>>>(e, src, dst, E, N);

    // Layer 1 (fused expand+edge)  <- ncu capture lands here (launch idx 3)
    k_layer<<<LB, TPB, smemL>>>(x, fgn_w1, fgn_b1, N, 0);
    k_node<0><<<NB, 256>>>(x, root1, bias1, N, 0, 1);   // -> d_h, agg=0

    // Layer 2
    k_layer<<<LB, TPB, smemL>>>(x, fgn_w2, fgn_b2, N, 1);
    k_node<1><<<NB, 256>>>(x, root2, bias2, N, 1, 0);   // -> d_pooled

    k_final<<<1, 32>>>(dw, db, (float*)d_out);
}